// round 1
// baseline (speedup 1.0000x reference)
#include <cuda_runtime.h>

#define NN 100000
#define NE 320000
#define DIN 256
#define DH  64
#define DO  4

// Scratch (device globals; no allocation allowed)
__device__ float g_y[NN * 128];     // x @ [W1_l | W1_r]  : cols 0..63 = l, 64..127 = r
__device__ float g_agg1[NN * 64];   // scatter-sum of y_l over in-edges
__device__ float g_z[NN * 8];       // h @ [W2_l | W2_r]  : 0..3 = l, 4..7 = r
__device__ float g_agg2[NN * 4];
__device__ float g_deg[NN];

// ---------------- degree ----------------
__global__ void deg_kernel(const int* __restrict__ dst, int E) {
    int e = blockIdx.x * blockDim.x + threadIdx.x;
    if (e < E) atomicAdd(&g_deg[dst[e]], 1.0f);
}

// ---------------- GEMM1: y[N,128] = x[N,256] @ [W1_l|W1_r] (no bias) ----------------
// Block: 256 threads, tile 64 rows x 128 cols, K-tiles of 32.
// Thread (tx,ty): tx in [0,32) -> 4 cols, ty in [0,8) -> 8 rows.
#define BR 64
#define KT 32
__global__ __launch_bounds__(256) void gemm1_kernel(
    const float* __restrict__ x,
    const float* __restrict__ Wl,
    const float* __restrict__ Wr,
    int N)
{
    __shared__ float xs[KT][BR + 1];   // [k][row], padded
    __shared__ float ws[KT][128];      // [k][col]
    const int tid = threadIdx.x;
    const int tx = tid & 31;
    const int ty = tid >> 5;
    const int row0 = blockIdx.x * BR;

    float acc[8][4];
#pragma unroll
    for (int i = 0; i < 8; i++)
#pragma unroll
        for (int j = 0; j < 4; j++) acc[i][j] = 0.0f;

    for (int kt = 0; kt < DIN; kt += KT) {
        // load x tile (64 rows x 32 k), transpose into xs[k][row]
#pragma unroll
        for (int it = 0; it < 8; ++it) {
            int idx = it * 256 + tid;
            int r = idx >> 5;       // 0..63
            int k = idx & 31;
            int grow = row0 + r;
            float v = (grow < N) ? x[(size_t)grow * DIN + kt + k] : 0.0f;
            xs[k][r] = v;
        }
        // load W tile (32 k x 128 cols) from the two weight matrices
#pragma unroll
        for (int it = 0; it < 16; ++it) {
            int idx = it * 256 + tid;
            int k = idx >> 7;       // 0..31
            int c = idx & 127;
            int gk = kt + k;
            float w = (c < DH) ? Wl[gk * DH + c] : Wr[gk * DH + (c - DH)];
            ws[k][c] = w;
        }
        __syncthreads();

#pragma unroll
        for (int k = 0; k < KT; ++k) {
            float a[8], b[4];
#pragma unroll
            for (int i = 0; i < 8; i++) a[i] = xs[k][ty * 8 + i];
#pragma unroll
            for (int j = 0; j < 4; j++) b[j] = ws[k][tx * 4 + j];
#pragma unroll
            for (int i = 0; i < 8; i++)
#pragma unroll
                for (int j = 0; j < 4; j++)
                    acc[i][j] = fmaf(a[i], b[j], acc[i][j]);
        }
        __syncthreads();
    }

#pragma unroll
    for (int i = 0; i < 8; i++) {
        int grow = row0 + ty * 8 + i;
        if (grow < N) {
            float4 v = make_float4(acc[i][0], acc[i][1], acc[i][2], acc[i][3]);
            *reinterpret_cast<float4*>(&g_y[(size_t)grow * 128 + tx * 4]) = v;
        }
    }
}

// ---------------- scatter 1: agg1[dst] += y_l[src] ----------------
__global__ void scatter1_kernel(const int* __restrict__ src,
                                const int* __restrict__ dst, int E) {
    int t = blockIdx.x * blockDim.x + threadIdx.x;
    if (t < E * 64) {
        int e = t >> 6;
        int c = t & 63;
        int s = src[e];
        int d = dst[e];
        atomicAdd(&g_agg1[(size_t)d * 64 + c], g_y[(size_t)s * 128 + c]);
    }
}

// ---------------- node 1: h = relu(normalize(agg1/deg + b1 + y_r)); z = h @ [W2_l|W2_r] ----------------
// One warp per node. lane handles dims c and c+32. h never hits memory.
__global__ __launch_bounds__(256) void node1_kernel(
    const float* __restrict__ b1,
    const float* __restrict__ W2l,   // [64,4]
    const float* __restrict__ W2r,   // [64,4]
    int N)
{
    int gw = (blockIdx.x * blockDim.x + threadIdx.x) >> 5;
    int lane = threadIdx.x & 31;
    if (gw >= N) return;

    float invd = 1.0f / fmaxf(g_deg[gw], 1.0f);
    float v0 = g_agg1[(size_t)gw * 64 + lane]      * invd + b1[lane]      + g_y[(size_t)gw * 128 + 64 + lane];
    float v1 = g_agg1[(size_t)gw * 64 + 32 + lane] * invd + b1[32 + lane] + g_y[(size_t)gw * 128 + 96 + lane];

    float ss = v0 * v0 + v1 * v1;
#pragma unroll
    for (int o = 16; o > 0; o >>= 1) ss += __shfl_xor_sync(0xFFFFFFFFu, ss, o);
    float scale = 1.0f / fmaxf(sqrtf(ss), 1e-12f);
    float h0 = fmaxf(v0 * scale, 0.0f);
    float h1 = fmaxf(v1 * scale, 0.0f);

    // z[j] = sum_c h[c] * W2cat[c][j],  j in [0,8)
    float zp[8];
#pragma unroll
    for (int j = 0; j < 8; j++) {
        float w0 = (j < 4) ? W2l[lane * 4 + j]        : W2r[lane * 4 + (j - 4)];
        float w1 = (j < 4) ? W2l[(lane + 32) * 4 + j] : W2r[(lane + 32) * 4 + (j - 4)];
        zp[j] = h0 * w0 + h1 * w1;
    }
#pragma unroll
    for (int j = 0; j < 8; j++) {
#pragma unroll
        for (int o = 16; o > 0; o >>= 1) zp[j] += __shfl_xor_sync(0xFFFFFFFFu, zp[j], o);
    }
    if (lane == 0) {
        float4 zl = make_float4(zp[0], zp[1], zp[2], zp[3]);
        float4 zr = make_float4(zp[4], zp[5], zp[6], zp[7]);
        *reinterpret_cast<float4*>(&g_z[(size_t)gw * 8])     = zl;
        *reinterpret_cast<float4*>(&g_z[(size_t)gw * 8 + 4]) = zr;
    }
}

// ---------------- scatter 2: agg2[dst] += z_l[src] ----------------
__global__ void scatter2_kernel(const int* __restrict__ src,
                                const int* __restrict__ dst, int E) {
    int e = blockIdx.x * blockDim.x + threadIdx.x;
    if (e < E) {
        int s = src[e];
        int d = dst[e];
        float4 zl = *reinterpret_cast<const float4*>(&g_z[(size_t)s * 8]);
        atomicAdd(&g_agg2[(size_t)d * 4 + 0], zl.x);
        atomicAdd(&g_agg2[(size_t)d * 4 + 1], zl.y);
        atomicAdd(&g_agg2[(size_t)d * 4 + 2], zl.z);
        atomicAdd(&g_agg2[(size_t)d * 4 + 3], zl.w);
    }
}

// ---------------- final: out = normalize(agg2/deg + b2 + z_r) ----------------
__global__ void node2_kernel(const float* __restrict__ b2,
                             float* __restrict__ out, int N) {
    int n = blockIdx.x * blockDim.x + threadIdx.x;
    if (n >= N) return;
    float invd = 1.0f / fmaxf(g_deg[n], 1.0f);
    float4 a  = *reinterpret_cast<const float4*>(&g_agg2[(size_t)n * 4]);
    float4 zr = *reinterpret_cast<const float4*>(&g_z[(size_t)n * 8 + 4]);
    float v0 = a.x * invd + b2[0] + zr.x;
    float v1 = a.y * invd + b2[1] + zr.y;
    float v2 = a.z * invd + b2[2] + zr.z;
    float v3 = a.w * invd + b2[3] + zr.w;
    float ss = v0 * v0 + v1 * v1 + v2 * v2 + v3 * v3;
    float scale = 1.0f / fmaxf(sqrtf(ss), 1e-12f);
    float4 o = make_float4(v0 * scale, v1 * scale, v2 * scale, v3 * scale);
    *reinterpret_cast<float4*>(&out[(size_t)n * 4]) = o;
}

extern "C" void kernel_launch(void* const* d_in, const int* in_sizes, int n_in,
                              void* d_out, int out_size) {
    const float* x   = (const float*)d_in[0];
    const int*   ei  = (const int*)  d_in[1];
    const float* W1l = (const float*)d_in[2];
    const float* b1l = (const float*)d_in[3];
    const float* W1r = (const float*)d_in[4];
    const float* W2l = (const float*)d_in[5];
    const float* b2l = (const float*)d_in[6];
    const float* W2r = (const float*)d_in[7];

    const int N = in_sizes[0] / DIN;     // 100000
    const int E = in_sizes[1] / 2;       // 320000
    const int* src = ei;
    const int* dst = ei + E;

    void *p_agg1, *p_agg2, *p_deg;
    cudaGetSymbolAddress(&p_agg1, g_agg1);
    cudaGetSymbolAddress(&p_agg2, g_agg2);
    cudaGetSymbolAddress(&p_deg,  g_deg);
    cudaMemsetAsync(p_agg1, 0, sizeof(float) * (size_t)N * 64);
    cudaMemsetAsync(p_agg2, 0, sizeof(float) * (size_t)N * 4);
    cudaMemsetAsync(p_deg,  0, sizeof(float) * (size_t)N);

    deg_kernel<<<(E + 255) / 256, 256>>>(dst, E);
    gemm1_kernel<<<(N + BR - 1) / BR, 256>>>(x, W1l, W1r, N);
    {
        long long tot = (long long)E * 64;
        int blocks = (int)((tot + 255) / 256);
        scatter1_kernel<<<blocks, 256>>>(src, dst, E);
    }
    node1_kernel<<<(N + 7) / 8, 256>>>(b1l, W2l, W2r, N);
    scatter2_kernel<<<(E + 255) / 256, 256>>>(src, dst, E);
    node2_kernel<<<(N + 255) / 256, 256>>>(b2l, (float*)d_out, N);
}

// round 2
// speedup vs baseline: 1.3167x; 1.3167x over previous
#include <cuda_runtime.h>

#define NN 100000
#define NE 320000
#define DIN 256
#define DH  64
#define DO  4

// Scratch (device globals; no allocation allowed)
__device__ float g_y[NN * 128];     // x @ [W1_l | W1_r]  : cols 0..63 = l, 64..127 = r
__device__ float g_agg1[NN * 64];   // scatter-sum of y_l over in-edges
__device__ float g_z[NN * 8];       // h @ [W2_l | W2_r]  : 0..3 = l, 4..7 = r
__device__ float g_agg2[NN * 4];
__device__ float g_deg[NN];

#define FMA_F32X2(d, a, b) \
    asm("fma.rn.f32x2 %0, %1, %2, %0;" : "+l"(d) : "l"(a), "l"(b))
#define PACK_F32X2(out, lo, hi) \
    asm("mov.b64 %0, {%1, %2};" : "=l"(out) : "f"(lo), "f"(hi))
#define UNPACK_F32X2(lo, hi, in) \
    asm("mov.b64 {%0, %1}, %2;" : "=f"(lo), "=f"(hi) : "l"(in))

// ---------------- degree ----------------
__global__ void deg_kernel(const int* __restrict__ dst, int E) {
    int e = blockIdx.x * blockDim.x + threadIdx.x;
    if (e < E) atomicAdd(&g_deg[dst[e]], 1.0f);
}

// ---------------- GEMM1: y[N,128] = x[N,256] @ [W1_l|W1_r] (no bias) ----------------
// Block: 256 threads, tile 64 rows x 128 cols, K-tiles of 32.
// Thread (tx,ty): tx in [0,32) -> 4 cols, ty in [0,8) -> 8 rows (as 4 f32x2 row-pairs).
#define BR 64
#define KT 32
#define XS_STRIDE (BR + 4)   // 68 floats = 272B: keeps rows 16B-aligned, 4-way write conflict only
__global__ __launch_bounds__(256) void gemm1_kernel(
    const float* __restrict__ x,
    const float* __restrict__ Wl,
    const float* __restrict__ Wr,
    int N)
{
    __shared__ __align__(16) float xs[KT][XS_STRIDE];   // [k][row]
    __shared__ __align__(16) float ws[KT][128];         // [k][col]
    const int tid = threadIdx.x;
    const int tx = tid & 31;
    const int ty = tid >> 5;
    const int row0 = blockIdx.x * BR;

    unsigned long long acc2[4][4];   // [row-pair][col], f32x2: lo=even row, hi=odd row
    {
        float z = 0.0f;
        unsigned long long zz; PACK_F32X2(zz, z, z);
#pragma unroll
        for (int p = 0; p < 4; p++)
#pragma unroll
            for (int j = 0; j < 4; j++) acc2[p][j] = zz;
    }

    for (int kt = 0; kt < DIN; kt += KT) {
        // load x tile (64 rows x 32 k), transpose into xs[k][row]
#pragma unroll
        for (int it = 0; it < 8; ++it) {
            int idx = it * 256 + tid;
            int r = idx >> 5;       // 0..63
            int k = idx & 31;
            int grow = row0 + r;
            float v = (grow < N) ? x[(size_t)grow * DIN + kt + k] : 0.0f;
            xs[k][r] = v;
        }
        // load W tile (32 k x 128 cols) from the two weight matrices
#pragma unroll
        for (int it = 0; it < 16; ++it) {
            int idx = it * 256 + tid;
            int k = idx >> 7;       // 0..31
            int c = idx & 127;
            int gk = kt + k;
            float w = (c < DH) ? Wl[gk * DH + c] : Wr[gk * DH + (c - DH)];
            ws[k][c] = w;
        }
        __syncthreads();

#pragma unroll
        for (int k = 0; k < KT; ++k) {
            // 8 row values as 4 packed pairs (broadcast loads: all lanes same addr)
            const ulonglong2* ap =
                reinterpret_cast<const ulonglong2*>(&xs[k][ty * 8]);
            ulonglong2 aA = ap[0];   // rows (0,1),(2,3)
            ulonglong2 aB = ap[1];   // rows (4,5),(6,7)
            float4 bv = *reinterpret_cast<const float4*>(&ws[k][tx * 4]);
            unsigned long long b2[4];
            PACK_F32X2(b2[0], bv.x, bv.x);
            PACK_F32X2(b2[1], bv.y, bv.y);
            PACK_F32X2(b2[2], bv.z, bv.z);
            PACK_F32X2(b2[3], bv.w, bv.w);
#pragma unroll
            for (int j = 0; j < 4; j++) {
                FMA_F32X2(acc2[0][j], aA.x, b2[j]);
                FMA_F32X2(acc2[1][j], aA.y, b2[j]);
                FMA_F32X2(acc2[2][j], aB.x, b2[j]);
                FMA_F32X2(acc2[3][j], aB.y, b2[j]);
            }
        }
        __syncthreads();
    }

#pragma unroll
    for (int p = 0; p < 4; p++) {
        float r0[4], r1[4];
#pragma unroll
        for (int j = 0; j < 4; j++) UNPACK_F32X2(r0[j], r1[j], acc2[p][j]);
        int g0 = row0 + ty * 8 + 2 * p;
        if (g0 < N)
            *reinterpret_cast<float4*>(&g_y[(size_t)g0 * 128 + tx * 4]) =
                make_float4(r0[0], r0[1], r0[2], r0[3]);
        if (g0 + 1 < N)
            *reinterpret_cast<float4*>(&g_y[(size_t)(g0 + 1) * 128 + tx * 4]) =
                make_float4(r1[0], r1[1], r1[2], r1[3]);
    }
}

// ---------------- scatter 1: agg1[dst] += y_l[src]  (vector red.v4) ----------------
__global__ void scatter1_kernel(const int* __restrict__ src,
                                const int* __restrict__ dst, int E) {
    int t = blockIdx.x * blockDim.x + threadIdx.x;
    if (t < E * 16) {
        int e = t >> 4;
        int c = (t & 15) * 4;
        int s = __ldg(&src[e]);
        int d = __ldg(&dst[e]);
        float4 v = *reinterpret_cast<const float4*>(&g_y[(size_t)s * 128 + c]);
        asm volatile("red.global.add.v4.f32 [%0], {%1, %2, %3, %4};"
                     :: "l"(&g_agg1[(size_t)d * 64 + c]),
                        "f"(v.x), "f"(v.y), "f"(v.z), "f"(v.w)
                     : "memory");
    }
}

// ---------------- node 1: h = relu(normalize(agg1/deg + b1 + y_r)); z = h @ [W2_l|W2_r] ----------------
// One warp per node. lane handles dims c and c+32. h never hits memory.
// 8-output reduction uses folding butterflies: 9 shuffles instead of 40.
__global__ __launch_bounds__(256) void node1_kernel(
    const float* __restrict__ b1,
    const float* __restrict__ W2l,   // [64,4]
    const float* __restrict__ W2r,   // [64,4]
    int N)
{
    int gw = (blockIdx.x * blockDim.x + threadIdx.x) >> 5;
    int lane = threadIdx.x & 31;
    if (gw >= N) return;

    float invd = 1.0f / fmaxf(g_deg[gw], 1.0f);
    float v0 = g_agg1[(size_t)gw * 64 + lane]        * invd + b1[lane]      + g_y[(size_t)gw * 128 + 64 + lane];
    float v1 = g_agg1[(size_t)gw * 64 + 32 + lane]   * invd + b1[32 + lane] + g_y[(size_t)gw * 128 + 96 + lane];

    float ss = v0 * v0 + v1 * v1;
#pragma unroll
    for (int o = 16; o > 0; o >>= 1) ss += __shfl_xor_sync(0xFFFFFFFFu, ss, o);
    float scale = 1.0f / fmaxf(sqrtf(ss), 1e-12f);
    float h0 = fmaxf(v0 * scale, 0.0f);
    float h1 = fmaxf(v1 * scale, 0.0f);

    // per-lane partials for all 8 outputs
    float zp[8];
#pragma unroll
    for (int j = 0; j < 8; j++) {
        float w0 = (j < 4) ? W2l[lane * 4 + j]        : W2r[lane * 4 + (j - 4)];
        float w1 = (j < 4) ? W2l[(lane + 32) * 4 + j] : W2r[(lane + 32) * 4 + (j - 4)];
        zp[j] = h0 * w0 + h1 * w1;
    }

    // folding reduction: halve live-value count at each butterfly step
    bool hi16 = (lane & 16) != 0;
    float v4[4];
#pragma unroll
    for (int jj = 0; jj < 4; jj++) {
        float send = hi16 ? zp[jj] : zp[jj + 4];
        float recv = __shfl_xor_sync(0xFFFFFFFFu, send, 16);
        v4[jj] = (hi16 ? zp[jj + 4] : zp[jj]) + recv;
    }
    bool hi8 = (lane & 8) != 0;
    float v2[2];
#pragma unroll
    for (int jj = 0; jj < 2; jj++) {
        float send = hi8 ? v4[jj] : v4[jj + 2];
        float recv = __shfl_xor_sync(0xFFFFFFFFu, send, 8);
        v2[jj] = (hi8 ? v4[jj + 2] : v4[jj]) + recv;
    }
    bool hi4 = (lane & 4) != 0;
    float w1v;
    {
        float send = hi4 ? v2[0] : v2[1];
        float recv = __shfl_xor_sync(0xFFFFFFFFu, send, 4);
        w1v = (hi4 ? v2[1] : v2[0]) + recv;
    }
    w1v += __shfl_xor_sync(0xFFFFFFFFu, w1v, 2);
    w1v += __shfl_xor_sync(0xFFFFFFFFu, w1v, 1);

    // lane holds z[j], j = 4*bit16 + 2*bit8 + bit4
    if ((lane & 3) == 0) {
        int j = ((lane >> 4) & 1) * 4 + ((lane >> 3) & 1) * 2 + ((lane >> 2) & 1);
        g_z[(size_t)gw * 8 + j] = w1v;
    }
}

// ---------------- scatter 2: agg2[dst] += z_l[src] (vector red.v4) ----------------
__global__ void scatter2_kernel(const int* __restrict__ src,
                                const int* __restrict__ dst, int E) {
    int e = blockIdx.x * blockDim.x + threadIdx.x;
    if (e < E) {
        int s = __ldg(&src[e]);
        int d = __ldg(&dst[e]);
        float4 zl = *reinterpret_cast<const float4*>(&g_z[(size_t)s * 8]);
        asm volatile("red.global.add.v4.f32 [%0], {%1, %2, %3, %4};"
                     :: "l"(&g_agg2[(size_t)d * 4]),
                        "f"(zl.x), "f"(zl.y), "f"(zl.z), "f"(zl.w)
                     : "memory");
    }
}

// ---------------- final: out = normalize(agg2/deg + b2 + z_r) ----------------
__global__ void node2_kernel(const float* __restrict__ b2,
                             float* __restrict__ out, int N) {
    int n = blockIdx.x * blockDim.x + threadIdx.x;
    if (n >= N) return;
    float invd = 1.0f / fmaxf(g_deg[n], 1.0f);
    float4 a  = *reinterpret_cast<const float4*>(&g_agg2[(size_t)n * 4]);
    float4 zr = *reinterpret_cast<const float4*>(&g_z[(size_t)n * 8 + 4]);
    float v0 = a.x * invd + b2[0] + zr.x;
    float v1 = a.y * invd + b2[1] + zr.y;
    float v2 = a.z * invd + b2[2] + zr.z;
    float v3 = a.w * invd + b2[3] + zr.w;
    float ss = v0 * v0 + v1 * v1 + v2 * v2 + v3 * v3;
    float scale = 1.0f / fmaxf(sqrtf(ss), 1e-12f);
    float4 o = make_float4(v0 * scale, v1 * scale, v2 * scale, v3 * scale);
    *reinterpret_cast<float4*>(&out[(size_t)n * 4]) = o;
}

extern "C" void kernel_launch(void* const* d_in, const int* in_sizes, int n_in,
                              void* d_out, int out_size) {
    const float* x   = (const float*)d_in[0];
    const int*   ei  = (const int*)  d_in[1];
    const float* W1l = (const float*)d_in[2];
    const float* b1l = (const float*)d_in[3];
    const float* W1r = (const float*)d_in[4];
    const float* W2l = (const float*)d_in[5];
    const float* b2l = (const float*)d_in[6];
    const float* W2r = (const float*)d_in[7];

    const int N = in_sizes[0] / DIN;     // 100000
    const int E = in_sizes[1] / 2;       // 320000
    const int* src = ei;
    const int* dst = ei + E;

    void *p_agg1, *p_agg2, *p_deg;
    cudaGetSymbolAddress(&p_agg1, g_agg1);
    cudaGetSymbolAddress(&p_agg2, g_agg2);
    cudaGetSymbolAddress(&p_deg,  g_deg);
    cudaMemsetAsync(p_agg1, 0, sizeof(float) * (size_t)N * 64);
    cudaMemsetAsync(p_agg2, 0, sizeof(float) * (size_t)N * 4);
    cudaMemsetAsync(p_deg,  0, sizeof(float) * (size_t)N);

    deg_kernel<<<(E + 255) / 256, 256>>>(dst, E);
    gemm1_kernel<<<(N + BR - 1) / BR, 256>>>(x, W1l, W1r, N);
    {
        long long tot = (long long)E * 16;
        int blocks = (int)((tot + 255) / 256);
        scatter1_kernel<<<blocks, 256>>>(src, dst, E);
    }
    node1_kernel<<<(N + 7) / 8, 256>>>(b1l, W2l, W2r, N);
    scatter2_kernel<<<(E + 255) / 256, 256>>>(src, dst, E);
    node2_kernel<<<(N + 255) / 256, 256>>>(b2l, (float*)d_out, N);
}

// round 4
// speedup vs baseline: 1.7764x; 1.3491x over previous
#include <cuda_runtime.h>
#include <cuda_bf16.h>
#include <cstdint>

#define NN 100000
#define NE 320000
#define DIN 256
#define DH  64
#define DO  4

// Scratch (device globals; no allocation allowed)
__device__ float g_y[NN * 128];        // x @ [W1_l | W1_r]
__device__ float g_agg1[NN * 64];
__device__ float g_z[NN * 8];
__device__ float g_agg2[NN * 4];
__device__ float g_deg[NN];
// B fragments, fragment-major: [(ntile*16+kstep)*32 + lane] = {bh0, bh1, bl0, bl1}
__device__ uint4 g_Bfrag[16 * 16 * 32];

// pack two f32 -> bf16x2 (elem0 = low 16 bits)
#define PACK_BF16X2(d, e0, e1) \
    asm("cvt.rn.bf16x2.f32 %0, %1, %2;" : "=r"(d) : "f"(e1), "f"(e0))

__device__ __forceinline__ void mma16816(float* d, const uint32_t* a,
                                         uint32_t b0, uint32_t b1) {
    asm volatile(
        "mma.sync.aligned.m16n8k16.row.col.f32.bf16.bf16.f32 "
        "{%0,%1,%2,%3},{%4,%5,%6,%7},{%8,%9},{%0,%1,%2,%3};"
        : "+f"(d[0]), "+f"(d[1]), "+f"(d[2]), "+f"(d[3])
        : "r"(a[0]), "r"(a[1]), "r"(a[2]), "r"(a[3]), "r"(b0), "r"(b1));
}

// ---------------- prep: W -> bf16 hi/lo mma fragments ----------------
__global__ void prep_bfrag_kernel(const float* __restrict__ Wl,
                                  const float* __restrict__ Wr) {
    int t = blockIdx.x * blockDim.x + threadIdx.x;   // 8192
    if (t >= 16 * 16 * 32) return;
    int lane = t & 31;
    int ks = (t >> 5) & 15;
    int nt = t >> 9;
    int n = nt * 8 + (lane >> 2);
    int k = ks * 16 + (lane & 3) * 2;
    const float* W = (n < DH) ? Wl : Wr;
    int nn = (n < DH) ? n : n - DH;
    float v[4] = { W[(k)     * DH + nn], W[(k + 1) * DH + nn],
                   W[(k + 8) * DH + nn], W[(k + 9) * DH + nn] };
    float h[4], l[4];
#pragma unroll
    for (int i = 0; i < 4; i++) {
        h[i] = __bfloat162float(__float2bfloat16(v[i]));
        l[i] = v[i] - h[i];
    }
    uint4 o;
    PACK_BF16X2(o.x, h[0], h[1]);
    PACK_BF16X2(o.y, h[2], h[3]);
    PACK_BF16X2(o.z, l[0], l[1]);
    PACK_BF16X2(o.w, l[2], l[3]);
    g_Bfrag[t] = o;
}

// ---------------- degree ----------------
__global__ void deg_kernel(const int* __restrict__ dst, int E) {
    int e = blockIdx.x * blockDim.x + threadIdx.x;
    if (e < E) atomicAdd(&g_deg[dst[e]], 1.0f);
}

// ---------------- GEMM1 via mma.sync bf16 split: y[N,128] = x[N,256] @ Wcat ----------------
// 8 warps/block, warp tile M=16 x N=128. No shared memory.
__global__ __launch_bounds__(256) void gemm1_hmma_kernel(const float* __restrict__ x, int N) {
    const int tid = threadIdx.x;
    const int wid = tid >> 5;
    const int lane = tid & 31;
    const int g = lane >> 2;       // group id (row within tile)
    const int q = lane & 3;        // thread in group (k / n pos)

    const int rowbase = blockIdx.x * 128 + wid * 16;
    const int r0 = rowbase + g;
    const int r1 = r0 + 8;
    const bool v0 = r0 < N;
    const bool v1 = r1 < N;
    const float* xr0 = x + (size_t)r0 * DIN;
    const float* xr1 = x + (size_t)r1 * DIN;

    float acc[16][4];
#pragma unroll
    for (int nt = 0; nt < 16; nt++)
#pragma unroll
        for (int j = 0; j < 4; j++) acc[nt][j] = 0.0f;

#pragma unroll 2
    for (int ks = 0; ks < 16; ++ks) {
        const int k0 = ks * 16 + q * 2;
        float2 xa = v0 ? *reinterpret_cast<const float2*>(xr0 + k0)     : make_float2(0.f, 0.f);
        float2 xb = v1 ? *reinterpret_cast<const float2*>(xr1 + k0)     : make_float2(0.f, 0.f);
        float2 xc = v0 ? *reinterpret_cast<const float2*>(xr0 + k0 + 8) : make_float2(0.f, 0.f);
        float2 xd = v1 ? *reinterpret_cast<const float2*>(xr1 + k0 + 8) : make_float2(0.f, 0.f);

        float ha, hb, hc, hd;
        uint32_t ah[4], al[4];
        // reg0: row g, cols k0,k0+1
        ha = __bfloat162float(__float2bfloat16(xa.x));
        hb = __bfloat162float(__float2bfloat16(xa.y));
        PACK_BF16X2(ah[0], ha, hb); PACK_BF16X2(al[0], xa.x - ha, xa.y - hb);
        // reg1: row g+8
        ha = __bfloat162float(__float2bfloat16(xb.x));
        hb = __bfloat162float(__float2bfloat16(xb.y));
        PACK_BF16X2(ah[1], ha, hb); PACK_BF16X2(al[1], xb.x - ha, xb.y - hb);
        // reg2: row g, cols k0+8,k0+9
        hc = __bfloat162float(__float2bfloat16(xc.x));
        hd = __bfloat162float(__float2bfloat16(xc.y));
        PACK_BF16X2(ah[2], hc, hd); PACK_BF16X2(al[2], xc.x - hc, xc.y - hd);
        // reg3: row g+8, cols k0+8,k0+9
        hc = __bfloat162float(__float2bfloat16(xd.x));
        hd = __bfloat162float(__float2bfloat16(xd.y));
        PACK_BF16X2(ah[3], hc, hd); PACK_BF16X2(al[3], xd.x - hc, xd.y - hd);

#pragma unroll
        for (int nt = 0; nt < 16; ++nt) {
            uint4 b = __ldg(&g_Bfrag[(nt * 16 + ks) * 32 + lane]);
            mma16816(acc[nt], ah, b.x, b.y);   // ah * bh
            mma16816(acc[nt], ah, b.z, b.w);   // ah * bl
            mma16816(acc[nt], al, b.x, b.y);   // al * bh
        }
    }

    // epilogue: d0/d1 -> row r0, d2/d3 -> row r1, cols nt*8 + q*2
    if (v0) {
        float* dp = &g_y[(size_t)r0 * 128];
#pragma unroll
        for (int nt = 0; nt < 16; ++nt)
            *reinterpret_cast<float2*>(dp + nt * 8 + q * 2) = make_float2(acc[nt][0], acc[nt][1]);
    }
    if (v1) {
        float* dp = &g_y[(size_t)r1 * 128];
#pragma unroll
        for (int nt = 0; nt < 16; ++nt)
            *reinterpret_cast<float2*>(dp + nt * 8 + q * 2) = make_float2(acc[nt][2], acc[nt][3]);
    }
}

// ---------------- scatter 1: agg1[dst] += y_l[src]  (vector red.v4) ----------------
__global__ void scatter1_kernel(const int* __restrict__ src,
                                const int* __restrict__ dst, int E) {
    int t = blockIdx.x * blockDim.x + threadIdx.x;
    if (t < E * 16) {
        int e = t >> 4;
        int c = (t & 15) * 4;
        int s = __ldg(&src[e]);
        int d = __ldg(&dst[e]);
        float4 v = *reinterpret_cast<const float4*>(&g_y[(size_t)s * 128 + c]);
        asm volatile("red.global.add.v4.f32 [%0], {%1, %2, %3, %4};"
                     :: "l"(&g_agg1[(size_t)d * 64 + c]),
                        "f"(v.x), "f"(v.y), "f"(v.z), "f"(v.w)
                     : "memory");
    }
}

// ---------------- node 1 ----------------
__global__ __launch_bounds__(256) void node1_kernel(
    const float* __restrict__ b1,
    const float* __restrict__ W2l,
    const float* __restrict__ W2r,
    int N)
{
    int gw = (blockIdx.x * blockDim.x + threadIdx.x) >> 5;
    int lane = threadIdx.x & 31;
    if (gw >= N) return;

    float invd = 1.0f / fmaxf(g_deg[gw], 1.0f);
    float v0 = g_agg1[(size_t)gw * 64 + lane]      * invd + b1[lane]      + g_y[(size_t)gw * 128 + 64 + lane];
    float v1 = g_agg1[(size_t)gw * 64 + 32 + lane] * invd + b1[32 + lane] + g_y[(size_t)gw * 128 + 96 + lane];

    float ss = v0 * v0 + v1 * v1;
#pragma unroll
    for (int o = 16; o > 0; o >>= 1) ss += __shfl_xor_sync(0xFFFFFFFFu, ss, o);
    float scale = 1.0f / fmaxf(sqrtf(ss), 1e-12f);
    float h0 = fmaxf(v0 * scale, 0.0f);
    float h1 = fmaxf(v1 * scale, 0.0f);

    float zp[8];
#pragma unroll
    for (int j = 0; j < 8; j++) {
        float w0 = (j < 4) ? W2l[lane * 4 + j]        : W2r[lane * 4 + (j - 4)];
        float w1 = (j < 4) ? W2l[(lane + 32) * 4 + j] : W2r[(lane + 32) * 4 + (j - 4)];
        zp[j] = h0 * w0 + h1 * w1;
    }
    bool hi16 = (lane & 16) != 0;
    float v4[4];
#pragma unroll
    for (int jj = 0; jj < 4; jj++) {
        float send = hi16 ? zp[jj] : zp[jj + 4];
        float recv = __shfl_xor_sync(0xFFFFFFFFu, send, 16);
        v4[jj] = (hi16 ? zp[jj + 4] : zp[jj]) + recv;
    }
    bool hi8 = (lane & 8) != 0;
    float v2[2];
#pragma unroll
    for (int jj = 0; jj < 2; jj++) {
        float send = hi8 ? v4[jj] : v4[jj + 2];
        float recv = __shfl_xor_sync(0xFFFFFFFFu, send, 8);
        v2[jj] = (hi8 ? v4[jj + 2] : v4[jj]) + recv;
    }
    bool hi4 = (lane & 4) != 0;
    float w1v;
    {
        float send = hi4 ? v2[0] : v2[1];
        float recv = __shfl_xor_sync(0xFFFFFFFFu, send, 4);
        w1v = (hi4 ? v2[1] : v2[0]) + recv;
    }
    w1v += __shfl_xor_sync(0xFFFFFFFFu, w1v, 2);
    w1v += __shfl_xor_sync(0xFFFFFFFFu, w1v, 1);

    if ((lane & 3) == 0) {
        int j = ((lane >> 4) & 1) * 4 + ((lane >> 3) & 1) * 2 + ((lane >> 2) & 1);
        g_z[(size_t)gw * 8 + j] = w1v;
    }
}

// ---------------- scatter 2 ----------------
__global__ void scatter2_kernel(const int* __restrict__ src,
                                const int* __restrict__ dst, int E) {
    int e = blockIdx.x * blockDim.x + threadIdx.x;
    if (e < E) {
        int s = __ldg(&src[e]);
        int d = __ldg(&dst[e]);
        float4 zl = *reinterpret_cast<const float4*>(&g_z[(size_t)s * 8]);
        asm volatile("red.global.add.v4.f32 [%0], {%1, %2, %3, %4};"
                     :: "l"(&g_agg2[(size_t)d * 4]),
                        "f"(zl.x), "f"(zl.y), "f"(zl.z), "f"(zl.w)
                     : "memory");
    }
}

// ---------------- final ----------------
__global__ void node2_kernel(const float* __restrict__ b2,
                             float* __restrict__ out, int N) {
    int n = blockIdx.x * blockDim.x + threadIdx.x;
    if (n >= N) return;
    float invd = 1.0f / fmaxf(g_deg[n], 1.0f);
    float4 a  = *reinterpret_cast<const float4*>(&g_agg2[(size_t)n * 4]);
    float4 zr = *reinterpret_cast<const float4*>(&g_z[(size_t)n * 8 + 4]);
    float v0 = a.x * invd + b2[0] + zr.x;
    float v1 = a.y * invd + b2[1] + zr.y;
    float v2 = a.z * invd + b2[2] + zr.z;
    float v3 = a.w * invd + b2[3] + zr.w;
    float ss = v0 * v0 + v1 * v1 + v2 * v2 + v3 * v3;
    float scale = 1.0f / fmaxf(sqrtf(ss), 1e-12f);
    *reinterpret_cast<float4*>(&out[(size_t)n * 4]) =
        make_float4(v0 * scale, v1 * scale, v2 * scale, v3 * scale);
}

extern "C" void kernel_launch(void* const* d_in, const int* in_sizes, int n_in,
                              void* d_out, int out_size) {
    const float* x   = (const float*)d_in[0];
    const int*   ei  = (const int*)  d_in[1];
    const float* W1l = (const float*)d_in[2];
    const float* b1l = (const float*)d_in[3];
    const float* W1r = (const float*)d_in[4];
    const float* W2l = (const float*)d_in[5];
    const float* b2l = (const float*)d_in[6];
    const float* W2r = (const float*)d_in[7];

    const int N = in_sizes[0] / DIN;
    const int E = in_sizes[1] / 2;
    const int* src = ei;
    const int* dst = ei + E;

    void *p_agg1, *p_agg2, *p_deg;
    cudaGetSymbolAddress(&p_agg1, g_agg1);
    cudaGetSymbolAddress(&p_agg2, g_agg2);
    cudaGetSymbolAddress(&p_deg,  g_deg);
    cudaMemsetAsync(p_agg1, 0, sizeof(float) * (size_t)N * 64);
    cudaMemsetAsync(p_agg2, 0, sizeof(float) * (size_t)N * 4);
    cudaMemsetAsync(p_deg,  0, sizeof(float) * (size_t)N);

    prep_bfrag_kernel<<<32, 256>>>(W1l, W1r);
    deg_kernel<<<(E + 255) / 256, 256>>>(dst, E);
    gemm1_hmma_kernel<<<(N + 127) / 128, 256>>>(x, N);
    {
        long long tot = (long long)E * 16;
        int blocks = (int)((tot + 255) / 256);
        scatter1_kernel<<<blocks, 256>>>(src, dst, E);
    }
    node1_kernel<<<(N + 7) / 8, 256>>>(b1l, W2l, W2r, N);
    scatter2_kernel<<<(E + 255) / 256, 256>>>(src, dst, E);
    node2_kernel<<<(N + 255) / 256, 256>>>(b2l, (float*)d_out, N);
}

// round 5
// speedup vs baseline: 1.8887x; 1.0632x over previous
#include <cuda_runtime.h>
#include <cuda_bf16.h>
#include <cstdint>

#define NN 100000
#define NE 320000
#define DIN 256
#define DH  64
#define DO  4

// Scratch (device globals; no allocation allowed)
__device__ float g_y[NN * 128];        // x @ [W1_l | W1_r]
__device__ float g_agg1[NN * 64];
__device__ float g_z[NN * 8];
__device__ float g_agg2[NN * 4];
__device__ float g_deg[NN];
// B fragments, fragment-major: [(ntile*16+kstep)*32 + lane] = {bh0, bh1, bl0, bl1}
__device__ uint4 g_Bfrag[16 * 16 * 32];

// pack two f32 -> bf16x2 (elem0 = low 16 bits)
#define PACK_BF16X2(d, e0, e1) \
    asm("cvt.rn.bf16x2.f32 %0, %1, %2;" : "=r"(d) : "f"(e1), "f"(e0))

__device__ __forceinline__ void mma16816(float* d, const uint32_t* a,
                                         uint32_t b0, uint32_t b1) {
    asm volatile(
        "mma.sync.aligned.m16n8k16.row.col.f32.bf16.bf16.f32 "
        "{%0,%1,%2,%3},{%4,%5,%6,%7},{%8,%9},{%0,%1,%2,%3};"
        : "+f"(d[0]), "+f"(d[1]), "+f"(d[2]), "+f"(d[3])
        : "r"(a[0]), "r"(a[1]), "r"(a[2]), "r"(a[3]), "r"(b0), "r"(b1));
}

// ---------------- prep: W -> bf16 hi/lo mma fragments ----------------
__global__ void prep_bfrag_kernel(const float* __restrict__ Wl,
                                  const float* __restrict__ Wr) {
    int t = blockIdx.x * blockDim.x + threadIdx.x;   // 8192
    if (t >= 16 * 16 * 32) return;
    int lane = t & 31;
    int ks = (t >> 5) & 15;
    int nt = t >> 9;
    int n = nt * 8 + (lane >> 2);
    int k = ks * 16 + (lane & 3) * 2;
    const float* W = (n < DH) ? Wl : Wr;
    int nn = (n < DH) ? n : n - DH;
    float v[4] = { W[(k)     * DH + nn], W[(k + 1) * DH + nn],
                   W[(k + 8) * DH + nn], W[(k + 9) * DH + nn] };
    float h[4], l[4];
#pragma unroll
    for (int i = 0; i < 4; i++) {
        h[i] = __bfloat162float(__float2bfloat16(v[i]));
        l[i] = v[i] - h[i];
    }
    uint4 o;
    PACK_BF16X2(o.x, h[0], h[1]);
    PACK_BF16X2(o.y, h[2], h[3]);
    PACK_BF16X2(o.z, l[0], l[1]);
    PACK_BF16X2(o.w, l[2], l[3]);
    g_Bfrag[t] = o;
}

// ---------------- degree (split in two launches for ncu alignment) ----------------
__global__ void deg_kernel(const int* __restrict__ dst, int e0, int e1) {
    int e = e0 + blockIdx.x * blockDim.x + threadIdx.x;
    if (e < e1) atomicAdd(&g_deg[dst[e]], 1.0f);
}

// ---------------- GEMM1 via mma.sync bf16 split: y[N,128] = x[N,256] @ Wcat ----------------
// 8 warps/block, warp tile M=16 x N=128. No shared memory.
__global__ __launch_bounds__(256) void gemm1_hmma_kernel(const float* __restrict__ x, int N) {
    const int tid = threadIdx.x;
    const int wid = tid >> 5;
    const int lane = tid & 31;
    const int g = lane >> 2;       // group id (row within tile)
    const int q = lane & 3;        // thread in group (k / n pos)

    const int rowbase = blockIdx.x * 128 + wid * 16;
    const int r0 = rowbase + g;
    const int r1 = r0 + 8;
    const bool v0 = r0 < N;
    const bool v1 = r1 < N;
    const float* xr0 = x + (size_t)r0 * DIN;
    const float* xr1 = x + (size_t)r1 * DIN;

    float acc[16][4];
#pragma unroll
    for (int nt = 0; nt < 16; nt++)
#pragma unroll
        for (int j = 0; j < 4; j++) acc[nt][j] = 0.0f;

#pragma unroll 2
    for (int ks = 0; ks < 16; ++ks) {
        const int k0 = ks * 16 + q * 2;
        float2 xa = v0 ? *reinterpret_cast<const float2*>(xr0 + k0)     : make_float2(0.f, 0.f);
        float2 xb = v1 ? *reinterpret_cast<const float2*>(xr1 + k0)     : make_float2(0.f, 0.f);
        float2 xc = v0 ? *reinterpret_cast<const float2*>(xr0 + k0 + 8) : make_float2(0.f, 0.f);
        float2 xd = v1 ? *reinterpret_cast<const float2*>(xr1 + k0 + 8) : make_float2(0.f, 0.f);

        float ha, hb, hc, hd;
        uint32_t ah[4], al[4];
        ha = __bfloat162float(__float2bfloat16(xa.x));
        hb = __bfloat162float(__float2bfloat16(xa.y));
        PACK_BF16X2(ah[0], ha, hb); PACK_BF16X2(al[0], xa.x - ha, xa.y - hb);
        ha = __bfloat162float(__float2bfloat16(xb.x));
        hb = __bfloat162float(__float2bfloat16(xb.y));
        PACK_BF16X2(ah[1], ha, hb); PACK_BF16X2(al[1], xb.x - ha, xb.y - hb);
        hc = __bfloat162float(__float2bfloat16(xc.x));
        hd = __bfloat162float(__float2bfloat16(xc.y));
        PACK_BF16X2(ah[2], hc, hd); PACK_BF16X2(al[2], xc.x - hc, xc.y - hd);
        hc = __bfloat162float(__float2bfloat16(xd.x));
        hd = __bfloat162float(__float2bfloat16(xd.y));
        PACK_BF16X2(ah[3], hc, hd); PACK_BF16X2(al[3], xd.x - hc, xd.y - hd);

#pragma unroll
        for (int nt = 0; nt < 16; ++nt) {
            uint4 b = __ldg(&g_Bfrag[(nt * 16 + ks) * 32 + lane]);
            mma16816(acc[nt], ah, b.x, b.y);   // ah * bh
            mma16816(acc[nt], ah, b.z, b.w);   // ah * bl
            mma16816(acc[nt], al, b.x, b.y);   // al * bh
        }
    }

    if (v0) {
        float* dp = &g_y[(size_t)r0 * 128];
#pragma unroll
        for (int nt = 0; nt < 16; ++nt)
            *reinterpret_cast<float2*>(dp + nt * 8 + q * 2) = make_float2(acc[nt][0], acc[nt][1]);
    }
    if (v1) {
        float* dp = &g_y[(size_t)r1 * 128];
#pragma unroll
        for (int nt = 0; nt < 16; ++nt)
            *reinterpret_cast<float2*>(dp + nt * 8 + q * 2) = make_float2(acc[nt][2], acc[nt][3]);
    }
}

// ---------------- scatter 1: agg1[dst] += y_l[src]  (vector red.v4) ----------------
__global__ void scatter1_kernel(const int* __restrict__ src,
                                const int* __restrict__ dst, int E) {
    int t = blockIdx.x * blockDim.x + threadIdx.x;
    if (t < E * 16) {
        int e = t >> 4;
        int c = (t & 15) * 4;
        int s = __ldg(&src[e]);
        int d = __ldg(&dst[e]);
        float4 v = *reinterpret_cast<const float4*>(&g_y[(size_t)s * 128 + c]);
        asm volatile("red.global.add.v4.f32 [%0], {%1, %2, %3, %4};"
                     :: "l"(&g_agg1[(size_t)d * 64 + c]),
                        "f"(v.x), "f"(v.y), "f"(v.z), "f"(v.w)
                     : "memory");
    }
}

// ---------------- node 1: thread-per-node, single pass ----------------
// relu(v*scale) = scale*relu(v) (scale>0), so ss and z-matvec fuse into one pass.
__global__ __launch_bounds__(256) void node1_kernel(
    const float* __restrict__ b1,
    const float* __restrict__ W2l,   // [64,4]
    const float* __restrict__ W2r,   // [64,4]
    int N)
{
    __shared__ float ws[64][8];
    __shared__ float b1s[64];
    int tid = threadIdx.x;
#pragma unroll
    for (int t = tid; t < 512; t += 256) {
        int k = t >> 3, j = t & 7;
        ws[k][j] = (j < 4) ? W2l[k * 4 + j] : W2r[k * 4 + (j - 4)];
    }
    if (tid < 64) b1s[tid] = b1[tid];
    __syncthreads();

    int n = blockIdx.x * 256 + tid;
    if (n >= N) return;

    float invd = 1.0f / fmaxf(g_deg[n], 1.0f);
    const float4* ar = reinterpret_cast<const float4*>(&g_agg1[(size_t)n * 64]);
    const float4* yr = reinterpret_cast<const float4*>(&g_y[(size_t)n * 128 + 64]);

    float z[8];
#pragma unroll
    for (int j = 0; j < 8; j++) z[j] = 0.0f;
    float ss = 0.0f;

#pragma unroll
    for (int c = 0; c < 16; ++c) {
        float4 a = ar[c];
        float4 y = yr[c];
        float v[4];
        v[0] = fmaf(a.x, invd, y.x + b1s[c * 4 + 0]);
        v[1] = fmaf(a.y, invd, y.y + b1s[c * 4 + 1]);
        v[2] = fmaf(a.z, invd, y.z + b1s[c * 4 + 2]);
        v[3] = fmaf(a.w, invd, y.w + b1s[c * 4 + 3]);
#pragma unroll
        for (int i = 0; i < 4; ++i) {
            ss = fmaf(v[i], v[i], ss);
            float r = fmaxf(v[i], 0.0f);
            const float4 w0 = *reinterpret_cast<const float4*>(&ws[c * 4 + i][0]);
            const float4 w1 = *reinterpret_cast<const float4*>(&ws[c * 4 + i][4]);
            z[0] = fmaf(r, w0.x, z[0]);
            z[1] = fmaf(r, w0.y, z[1]);
            z[2] = fmaf(r, w0.z, z[2]);
            z[3] = fmaf(r, w0.w, z[3]);
            z[4] = fmaf(r, w1.x, z[4]);
            z[5] = fmaf(r, w1.y, z[5]);
            z[6] = fmaf(r, w1.z, z[6]);
            z[7] = fmaf(r, w1.w, z[7]);
        }
    }

    float scale = 1.0f / fmaxf(sqrtf(ss), 1e-12f);
    float* zp = &g_z[(size_t)n * 8];
    *reinterpret_cast<float4*>(zp) =
        make_float4(z[0] * scale, z[1] * scale, z[2] * scale, z[3] * scale);
    *reinterpret_cast<float4*>(zp + 4) =
        make_float4(z[4] * scale, z[5] * scale, z[6] * scale, z[7] * scale);
}

// ---------------- scatter 2 ----------------
__global__ void scatter2_kernel(const int* __restrict__ src,
                                const int* __restrict__ dst, int E) {
    int e = blockIdx.x * blockDim.x + threadIdx.x;
    if (e < E) {
        int s = __ldg(&src[e]);
        int d = __ldg(&dst[e]);
        float4 zl = *reinterpret_cast<const float4*>(&g_z[(size_t)s * 8]);
        asm volatile("red.global.add.v4.f32 [%0], {%1, %2, %3, %4};"
                     :: "l"(&g_agg2[(size_t)d * 4]),
                        "f"(zl.x), "f"(zl.y), "f"(zl.z), "f"(zl.w)
                     : "memory");
    }
}

// ---------------- final ----------------
__global__ void node2_kernel(const float* __restrict__ b2,
                             float* __restrict__ out, int N) {
    int n = blockIdx.x * blockDim.x + threadIdx.x;
    if (n >= N) return;
    float invd = 1.0f / fmaxf(g_deg[n], 1.0f);
    float4 a  = *reinterpret_cast<const float4*>(&g_agg2[(size_t)n * 4]);
    float4 zr = *reinterpret_cast<const float4*>(&g_z[(size_t)n * 8 + 4]);
    float v0 = a.x * invd + b2[0] + zr.x;
    float v1 = a.y * invd + b2[1] + zr.y;
    float v2 = a.z * invd + b2[2] + zr.z;
    float v3 = a.w * invd + b2[3] + zr.w;
    float ss = v0 * v0 + v1 * v1 + v2 * v2 + v3 * v3;
    float scale = 1.0f / fmaxf(sqrtf(ss), 1e-12f);
    *reinterpret_cast<float4*>(&out[(size_t)n * 4]) =
        make_float4(v0 * scale, v1 * scale, v2 * scale, v3 * scale);
}

extern "C" void kernel_launch(void* const* d_in, const int* in_sizes, int n_in,
                              void* d_out, int out_size) {
    const float* x   = (const float*)d_in[0];
    const int*   ei  = (const int*)  d_in[1];
    const float* W1l = (const float*)d_in[2];
    const float* b1l = (const float*)d_in[3];
    const float* W1r = (const float*)d_in[4];
    const float* W2l = (const float*)d_in[5];
    const float* b2l = (const float*)d_in[6];
    const float* W2r = (const float*)d_in[7];

    const int N = in_sizes[0] / DIN;
    const int E = in_sizes[1] / 2;
    const int* src = ei;
    const int* dst = ei + E;

    void *p_agg1, *p_agg2, *p_deg;
    cudaGetSymbolAddress(&p_agg1, g_agg1);
    cudaGetSymbolAddress(&p_agg2, g_agg2);
    cudaGetSymbolAddress(&p_deg,  g_deg);
    cudaMemsetAsync(p_agg1, 0, sizeof(float) * (size_t)N * 64);
    cudaMemsetAsync(p_agg2, 0, sizeof(float) * (size_t)N * 4);
    cudaMemsetAsync(p_deg,  0, sizeof(float) * (size_t)N);

    prep_bfrag_kernel<<<32, 256>>>(W1l, W1r);
    // deg split into two launches so gemm1 is the 7th launch (ncu captures #7)
    int Eh = E / 2;
    deg_kernel<<<(Eh + 255) / 256, 256>>>(dst, 0, Eh);
    deg_kernel<<<(E - Eh + 255) / 256, 256>>>(dst, Eh, E);
    gemm1_hmma_kernel<<<(N + 127) / 128, 256>>>(x, N);
    {
        long long tot = (long long)E * 16;
        int blocks = (int)((tot + 255) / 256);
        scatter1_kernel<<<blocks, 256>>>(src, dst, E);
    }
    node1_kernel<<<(N + 255) / 256, 256>>>(b1l, W2l, W2r, N);
    scatter2_kernel<<<(E + 255) / 256, 256>>>(src, dst, E);
    node2_kernel<<<(N + 255) / 256, 256>>>(b2l, (float*)d_out, N);
}

// round 6
// speedup vs baseline: 2.2106x; 1.1704x over previous
#include <cuda_runtime.h>
#include <cuda_bf16.h>
#include <cstdint>

#define NN 100000
#define NE 320000
#define DIN 256
#define DH  64
#define DO  4

// Scratch (device globals; no allocation allowed)
__device__ float g_y[NN * 128];        // x @ [W1_l | W1_r]
__device__ float g_agg1[NN * 64];
__device__ float g_z[NN * 8];
__device__ float g_agg2[NN * 4];
__device__ float g_deg[NN];
// B fragments, fragment-major: [(ntile*16+kstep)*32 + lane] = {bh0, bh1, bl0, bl1}
__device__ uint4 g_Bfrag[16 * 16 * 32];

// pack two f32 -> bf16x2 (elem0 = low 16 bits)
#define PACK_BF16X2(d, e0, e1) \
    asm("cvt.rn.bf16x2.f32 %0, %1, %2;" : "=r"(d) : "f"(e1), "f"(e0))

__device__ __forceinline__ void mma16816(float* d, const uint32_t* a,
                                         uint32_t b0, uint32_t b1) {
    asm volatile(
        "mma.sync.aligned.m16n8k16.row.col.f32.bf16.bf16.f32 "
        "{%0,%1,%2,%3},{%4,%5,%6,%7},{%8,%9},{%0,%1,%2,%3};"
        : "+f"(d[0]), "+f"(d[1]), "+f"(d[2]), "+f"(d[3])
        : "r"(a[0]), "r"(a[1]), "r"(a[2]), "r"(a[3]), "r"(b0), "r"(b1));
}

// ---------------- prep: W -> bf16 hi/lo mma fragments ----------------
__global__ void prep_bfrag_kernel(const float* __restrict__ Wl,
                                  const float* __restrict__ Wr) {
    int t = blockIdx.x * blockDim.x + threadIdx.x;   // 8192
    if (t >= 16 * 16 * 32) return;
    int lane = t & 31;
    int ks = (t >> 5) & 15;
    int nt = t >> 9;
    int n = nt * 8 + (lane >> 2);
    int k = ks * 16 + (lane & 3) * 2;
    const float* W = (n < DH) ? Wl : Wr;
    int nn = (n < DH) ? n : n - DH;
    float v[4] = { W[(k)     * DH + nn], W[(k + 1) * DH + nn],
                   W[(k + 8) * DH + nn], W[(k + 9) * DH + nn] };
    float h[4], l[4];
#pragma unroll
    for (int i = 0; i < 4; i++) {
        h[i] = __bfloat162float(__float2bfloat16(v[i]));
        l[i] = v[i] - h[i];
    }
    uint4 o;
    PACK_BF16X2(o.x, h[0], h[1]);
    PACK_BF16X2(o.y, h[2], h[3]);
    PACK_BF16X2(o.z, l[0], l[1]);
    PACK_BF16X2(o.w, l[2], l[3]);
    g_Bfrag[t] = o;
}

// ---------------- degree (split in two launches for ncu alignment) ----------------
__global__ void deg_kernel(const int* __restrict__ dst, int e0, int e1) {
    int e = e0 + blockIdx.x * blockDim.x + threadIdx.x;
    if (e < e1) atomicAdd(&g_deg[dst[e]], 1.0f);
}

// ---------------- GEMM1 via mma.sync bf16 split: y[N,128] = x[N,256] @ Wcat ----------------
// 8 warps/block. Warp tile M=16 x N=64. Block = 64 rows x 128 cols
// (warps 0-3: N-half 0, warps 4-7: N-half 1). Prefetched x, 2 blocks/SM.
__global__ __launch_bounds__(256, 2) void gemm1_hmma_kernel(const float* __restrict__ x, int N) {
    const int tid = threadIdx.x;
    const int wid = tid >> 5;
    const int lane = tid & 31;
    const int g = lane >> 2;       // row within tile
    const int q = lane & 3;        // k / n pos
    const int h = wid >> 2;        // N-half
    const int mw = wid & 3;        // M-tile

    const int rowbase = blockIdx.x * 64 + mw * 16;
    const int r0 = rowbase + g;
    const int r1 = r0 + 8;
    const bool v0 = r0 < N;
    const bool v1 = r1 < N;
    const float* xr0 = x + (size_t)r0 * DIN;
    const float* xr1 = x + (size_t)r1 * DIN;

    float acc[8][4];
#pragma unroll
    for (int nt = 0; nt < 8; nt++)
#pragma unroll
        for (int j = 0; j < 4; j++) acc[nt][j] = 0.0f;

    // prefetch ks=0
    float2 pa, pb, pc, pd;
    {
        const int k0 = q * 2;
        pa = v0 ? *reinterpret_cast<const float2*>(xr0 + k0)     : make_float2(0.f, 0.f);
        pb = v1 ? *reinterpret_cast<const float2*>(xr1 + k0)     : make_float2(0.f, 0.f);
        pc = v0 ? *reinterpret_cast<const float2*>(xr0 + k0 + 8) : make_float2(0.f, 0.f);
        pd = v1 ? *reinterpret_cast<const float2*>(xr1 + k0 + 8) : make_float2(0.f, 0.f);
    }

#pragma unroll
    for (int ks = 0; ks < 16; ++ks) {
        float ha, hb;
        uint32_t ah[4], al[4];
        ha = __bfloat162float(__float2bfloat16(pa.x));
        hb = __bfloat162float(__float2bfloat16(pa.y));
        PACK_BF16X2(ah[0], ha, hb); PACK_BF16X2(al[0], pa.x - ha, pa.y - hb);
        ha = __bfloat162float(__float2bfloat16(pb.x));
        hb = __bfloat162float(__float2bfloat16(pb.y));
        PACK_BF16X2(ah[1], ha, hb); PACK_BF16X2(al[1], pb.x - ha, pb.y - hb);
        ha = __bfloat162float(__float2bfloat16(pc.x));
        hb = __bfloat162float(__float2bfloat16(pc.y));
        PACK_BF16X2(ah[2], ha, hb); PACK_BF16X2(al[2], pc.x - ha, pc.y - hb);
        ha = __bfloat162float(__float2bfloat16(pd.x));
        hb = __bfloat162float(__float2bfloat16(pd.y));
        PACK_BF16X2(ah[3], ha, hb); PACK_BF16X2(al[3], pd.x - ha, pd.y - hb);

        if (ks < 15) {   // prefetch next k-step; overlaps with MMA burst below
            const int k0 = (ks + 1) * 16 + q * 2;
            pa = v0 ? *reinterpret_cast<const float2*>(xr0 + k0)     : make_float2(0.f, 0.f);
            pb = v1 ? *reinterpret_cast<const float2*>(xr1 + k0)     : make_float2(0.f, 0.f);
            pc = v0 ? *reinterpret_cast<const float2*>(xr0 + k0 + 8) : make_float2(0.f, 0.f);
            pd = v1 ? *reinterpret_cast<const float2*>(xr1 + k0 + 8) : make_float2(0.f, 0.f);
        }

#pragma unroll
        for (int nt = 0; nt < 8; ++nt) {
            uint4 b = __ldg(&g_Bfrag[((h * 8 + nt) * 16 + ks) * 32 + lane]);
            mma16816(acc[nt], ah, b.x, b.y);   // ah * bh
            mma16816(acc[nt], ah, b.z, b.w);   // ah * bl
            mma16816(acc[nt], al, b.x, b.y);   // al * bh
        }
    }

    if (v0) {
        float* dp = &g_y[(size_t)r0 * 128 + h * 64];
#pragma unroll
        for (int nt = 0; nt < 8; ++nt)
            *reinterpret_cast<float2*>(dp + nt * 8 + q * 2) = make_float2(acc[nt][0], acc[nt][1]);
    }
    if (v1) {
        float* dp = &g_y[(size_t)r1 * 128 + h * 64];
#pragma unroll
        for (int nt = 0; nt < 8; ++nt)
            *reinterpret_cast<float2*>(dp + nt * 8 + q * 2) = make_float2(acc[nt][2], acc[nt][3]);
    }
}

// ---------------- scatter 1: agg1[dst] += y_l[src]  (vector red.v4) ----------------
__global__ void scatter1_kernel(const int* __restrict__ src,
                                const int* __restrict__ dst, int E) {
    int t = blockIdx.x * blockDim.x + threadIdx.x;
    if (t < E * 16) {
        int e = t >> 4;
        int c = (t & 15) * 4;
        int s = __ldg(&src[e]);
        int d = __ldg(&dst[e]);
        float4 v = *reinterpret_cast<const float4*>(&g_y[(size_t)s * 128 + c]);
        asm volatile("red.global.add.v4.f32 [%0], {%1, %2, %3, %4};"
                     :: "l"(&g_agg1[(size_t)d * 64 + c]),
                        "f"(v.x), "f"(v.y), "f"(v.z), "f"(v.w)
                     : "memory");
    }
}

// ---------------- node 1: thread-per-node, single pass ----------------
__global__ __launch_bounds__(256) void node1_kernel(
    const float* __restrict__ b1,
    const float* __restrict__ W2l,   // [64,4]
    const float* __restrict__ W2r,   // [64,4]
    int N)
{
    __shared__ float ws[64][8];
    __shared__ float b1s[64];
    int tid = threadIdx.x;
#pragma unroll
    for (int t = tid; t < 512; t += 256) {
        int k = t >> 3, j = t & 7;
        ws[k][j] = (j < 4) ? W2l[k * 4 + j] : W2r[k * 4 + (j - 4)];
    }
    if (tid < 64) b1s[tid] = b1[tid];
    __syncthreads();

    int n = blockIdx.x * 256 + tid;
    if (n >= N) return;

    float invd = 1.0f / fmaxf(g_deg[n], 1.0f);
    const float4* ar = reinterpret_cast<const float4*>(&g_agg1[(size_t)n * 64]);
    const float4* yr = reinterpret_cast<const float4*>(&g_y[(size_t)n * 128 + 64]);

    float z[8];
#pragma unroll
    for (int j = 0; j < 8; j++) z[j] = 0.0f;
    float ss = 0.0f;

#pragma unroll
    for (int c = 0; c < 16; ++c) {
        float4 a = ar[c];
        float4 y = yr[c];
        float v[4];
        v[0] = fmaf(a.x, invd, y.x + b1s[c * 4 + 0]);
        v[1] = fmaf(a.y, invd, y.y + b1s[c * 4 + 1]);
        v[2] = fmaf(a.z, invd, y.z + b1s[c * 4 + 2]);
        v[3] = fmaf(a.w, invd, y.w + b1s[c * 4 + 3]);
#pragma unroll
        for (int i = 0; i < 4; ++i) {
            ss = fmaf(v[i], v[i], ss);
            float r = fmaxf(v[i], 0.0f);
            const float4 w0 = *reinterpret_cast<const float4*>(&ws[c * 4 + i][0]);
            const float4 w1 = *reinterpret_cast<const float4*>(&ws[c * 4 + i][4]);
            z[0] = fmaf(r, w0.x, z[0]);
            z[1] = fmaf(r, w0.y, z[1]);
            z[2] = fmaf(r, w0.z, z[2]);
            z[3] = fmaf(r, w0.w, z[3]);
            z[4] = fmaf(r, w1.x, z[4]);
            z[5] = fmaf(r, w1.y, z[5]);
            z[6] = fmaf(r, w1.z, z[6]);
            z[7] = fmaf(r, w1.w, z[7]);
        }
    }

    float scale = 1.0f / fmaxf(sqrtf(ss), 1e-12f);
    float* zp = &g_z[(size_t)n * 8];
    *reinterpret_cast<float4*>(zp) =
        make_float4(z[0] * scale, z[1] * scale, z[2] * scale, z[3] * scale);
    *reinterpret_cast<float4*>(zp + 4) =
        make_float4(z[4] * scale, z[5] * scale, z[6] * scale, z[7] * scale);
}

// ---------------- scatter 2 ----------------
__global__ void scatter2_kernel(const int* __restrict__ src,
                                const int* __restrict__ dst, int E) {
    int e = blockIdx.x * blockDim.x + threadIdx.x;
    if (e < E) {
        int s = __ldg(&src[e]);
        int d = __ldg(&dst[e]);
        float4 zl = *reinterpret_cast<const float4*>(&g_z[(size_t)s * 8]);
        asm volatile("red.global.add.v4.f32 [%0], {%1, %2, %3, %4};"
                     :: "l"(&g_agg2[(size_t)d * 4]),
                        "f"(zl.x), "f"(zl.y), "f"(zl.z), "f"(zl.w)
                     : "memory");
    }
}

// ---------------- final ----------------
__global__ void node2_kernel(const float* __restrict__ b2,
                             float* __restrict__ out, int N) {
    int n = blockIdx.x * blockDim.x + threadIdx.x;
    if (n >= N) return;
    float invd = 1.0f / fmaxf(g_deg[n], 1.0f);
    float4 a  = *reinterpret_cast<const float4*>(&g_agg2[(size_t)n * 4]);
    float4 zr = *reinterpret_cast<const float4*>(&g_z[(size_t)n * 8 + 4]);
    float v0 = a.x * invd + b2[0] + zr.x;
    float v1 = a.y * invd + b2[1] + zr.y;
    float v2 = a.z * invd + b2[2] + zr.z;
    float v3 = a.w * invd + b2[3] + zr.w;
    float ss = v0 * v0 + v1 * v1 + v2 * v2 + v3 * v3;
    float scale = 1.0f / fmaxf(sqrtf(ss), 1e-12f);
    *reinterpret_cast<float4*>(&out[(size_t)n * 4]) =
        make_float4(v0 * scale, v1 * scale, v2 * scale, v3 * scale);
}

extern "C" void kernel_launch(void* const* d_in, const int* in_sizes, int n_in,
                              void* d_out, int out_size) {
    const float* x   = (const float*)d_in[0];
    const int*   ei  = (const int*)  d_in[1];
    const float* W1l = (const float*)d_in[2];
    const float* b1l = (const float*)d_in[3];
    const float* W1r = (const float*)d_in[4];
    const float* W2l = (const float*)d_in[5];
    const float* b2l = (const float*)d_in[6];
    const float* W2r = (const float*)d_in[7];

    const int N = in_sizes[0] / DIN;
    const int E = in_sizes[1] / 2;
    const int* src = ei;
    const int* dst = ei + E;

    void *p_agg1, *p_agg2, *p_deg;
    cudaGetSymbolAddress(&p_agg1, g_agg1);
    cudaGetSymbolAddress(&p_agg2, g_agg2);
    cudaGetSymbolAddress(&p_deg,  g_deg);
    cudaMemsetAsync(p_agg1, 0, sizeof(float) * (size_t)N * 64);
    cudaMemsetAsync(p_agg2, 0, sizeof(float) * (size_t)N * 4);
    cudaMemsetAsync(p_deg,  0, sizeof(float) * (size_t)N);

    prep_bfrag_kernel<<<32, 256>>>(W1l, W1r);
    // deg split into two launches keeps gemm1 on the ncu capture slot
    int Eh = E / 2;
    deg_kernel<<<(Eh + 255) / 256, 256>>>(dst, 0, Eh);
    deg_kernel<<<(E - Eh + 255) / 256, 256>>>(dst, Eh, E);
    gemm1_hmma_kernel<<<(N + 63) / 64, 256>>>(x, N);
    {
        long long tot = (long long)E * 16;
        int blocks = (int)((tot + 255) / 256);
        scatter1_kernel<<<blocks, 256>>>(src, dst, E);
    }
    node1_kernel<<<(N + 255) / 256, 256>>>(b1l, W2l, W2r, N);
    scatter2_kernel<<<(E + 255) / 256, 256>>>(src, dst, E);
    node2_kernel<<<(N + 255) / 256, 256>>>(b2l, (float*)d_out, N);
}